// round 7
// baseline (speedup 1.0000x reference)
#include <cuda_runtime.h>
#include <math_constants.h>

// Problem constants (fixed shapes from reference)
#define KB 32          // batch
#define KT 8192        // time
#define KC 256         // channels
#define KW 21          // windows: 1 + 4 + 16
#define CHUNK 128      // rows per CTA (prologue amortized over 4x32-row blocks)
#define NQ  64         // float4 quads per row (KC/4)
#define NTHREADS 64    // 1 thread = 1 quad; every thread sees every row
#define SENT 0x7fffffff

__device__ __forceinline__ void atomic_max_f32(float* addr, float v) {
    // Order-isomorphic int trick; correct for all non-NaN floats.
    if (v >= 0.0f) {
        atomicMax(reinterpret_cast<int*>(addr), __float_as_int(v));
    } else {
        atomicMin(reinterpret_cast<unsigned int*>(addr), __float_as_uint(v));
    }
}

__global__ void spp_init_kernel(float* __restrict__ out, int n) {
    int i = blockIdx.x * blockDim.x + threadIdx.x;
    if (i < n) out[i] = -CUDART_INF_F;
}

__device__ __forceinline__ float4 f4max(float4 a, float4 b) {
    a.x = fmaxf(a.x, b.x);
    a.y = fmaxf(a.y, b.y);
    a.z = fmaxf(a.z, b.z);
    a.w = fmaxf(a.w, b.w);
    return a;
}
__device__ __forceinline__ float4 f4ninf() {
    return make_float4(-CUDART_INF_F, -CUDART_INF_F, -CUDART_INF_F, -CUDART_INF_F);
}

// Per-level window state machine (registers; warp-uniform except acc).
struct Win {
    int n;        // ndiv
    int dl;       // window length
    float stepf;  // (L - dl)/(n-1) in f32, matching reference exactly
    int i, s, e;  // current window index + bounds (SENT,SENT when exhausted)
    float4 acc;
};

__device__ __forceinline__ int win_start(const Win& w, int i) {
    // Exact replication of reference: round(step * i), f32, half-even.
    return (int)rintf(__fmul_rn(w.stepf, (float)i));
}

__device__ __forceinline__ void win_flush(const Win& w, float* out_lvl, int quad) {
    float* o = out_lvl + w.i * KC + quad * 4;
    atomic_max_f32(o + 0, w.acc.x);
    atomic_max_f32(o + 1, w.acc.y);
    atomic_max_f32(o + 2, w.acc.z);
    atomic_max_f32(o + 3, w.acc.w);
}

__device__ __forceinline__ void win_init(Win& w, int n, float Lf, int t0) {
    w.n = n;
    // div_len = ceil(L/n - 1e-8); 1/n mul is exact (n = 4, 16).
    float dlf = ceilf(__fmul_rn(Lf, 1.0f / (float)n) - 1e-8f);
    w.dl = (int)dlf;
    w.stepf = __fdiv_rn(Lf - dlf, (float)(n - 1));
    // Smallest i with end_i > t0 (estimate + exact fixup; loops are short).
    int i = 0;
    if (w.stepf > 0.0f) {
        i = (int)floorf(__fdiv_rn((float)(t0 - w.dl), w.stepf)) + 1;
        i = max(0, min(i, n - 1));
    }
    while (i > 0 && win_start(w, i - 1) + w.dl > t0) i--;
    while (i < n - 1 && win_start(w, i) + w.dl <= t0) i++;
    w.i = i;
    w.s = win_start(w, i);
    w.e = w.s + w.dl;
    if (w.e <= t0) { w.s = SENT; w.e = SENT; }   // defensive
    w.acc = f4ninf();
}

// All rows < t processed and t >= w.e: flush, advance to window live at t,
// back-filling already-streamed rows from L1/L2. Handles overlaps exactly.
__device__ __forceinline__ void win_advance(Win& w, int t, int t0,
                                            const float4* __restrict__ srcq,
                                            float* out_lvl, int quad) {
    win_flush(w, out_lvl, quad);
    for (;;) {
        if (w.i >= w.n - 1) { w.s = SENT; w.e = SENT; w.acc = f4ninf(); return; }
        w.i++;
        int ns = win_start(w, w.i);
        int ne = ns + w.dl;
        float4 a = f4ninf();
        int rb = max(ns, t0), re = min(ne, t);
        for (int r = rb; r < re; r++)
            a = f4max(a, __ldg(&srcq[r * NQ]));       // cache hits
        w.acc = a; w.s = ns; w.e = ne;
        if (ne > t) return;
        win_flush(w, out_lvl, quad);                  // tiny-L degenerate case
    }
}

// End-of-chunk drain: flush current window, then any later windows starting
// before t1 (rows already streamed -> cache back-fill).
__device__ __forceinline__ void win_drain(Win& w, int t0, int t1,
                                          const float4* __restrict__ srcq,
                                          float* out_lvl, int quad) {
    if (w.e == SENT) return;
    win_flush(w, out_lvl, quad);
    while (w.i < w.n - 1) {
        w.i++;
        int ns = win_start(w, w.i);
        if (ns >= t1) break;
        int re = min(ns + w.dl, t1);
        float4 a = f4ninf();
        for (int r = max(ns, t0); r < re; r++)
            a = f4max(a, __ldg(&srcq[r * NQ]));
        w.acc = a;
        win_flush(w, out_lvl, quad);
    }
}

__global__ __launch_bounds__(NTHREADS) void spp_kernel(
    const float4* __restrict__ seq,     // [B, T, NQ]
    const int* __restrict__ lengths,    // [B]
    float* __restrict__ out)            // [B, W, C]
{
    const int b  = blockIdx.y;
    const int L  = __ldg(&lengths[b]);
    const int T0 = blockIdx.x * CHUNK;
    if (T0 >= L) return;
    const int Tend = min(T0 + CHUNK, L);
    const int quad = threadIdx.x;

    const float4* srcq = seq + (size_t)b * KT * NQ + quad;  // row r -> srcq[r*NQ]
    const float Lf = (float)L;

    float* out_b  = out + (size_t)b * KW * KC;
    float* out_l1 = out_b + 1 * KC;   // windows 1..4
    float* out_l2 = out_b + 5 * KC;   // windows 5..20

    Win w1, w2;
    win_init(w1, 4,  Lf, T0);
    win_init(w2, 16, Lf, T0);

    float4 acc0 = f4ninf();           // level-0 window [0, L) covers every row

    // Segmented single streaming pass over the whole chunk. Inside a segment,
    // window membership is constant; full 32-row aligned blocks use the
    // unrolled immediate-offset path (one block max, then 3 cheap merges).
    int t = T0;
    while (t < Tend) {
        int seg = Tend;
        if (w1.e < seg) seg = w1.e;
        if (w1.s > t)   seg = min(seg, w1.s);
        if (w2.e < seg) seg = w2.e;
        if (w2.s > t)   seg = min(seg, w2.s);

        const bool in1 = (t >= w1.s);
        const bool in2 = (t >= w2.s);
        float4 a0 = acc0, a1 = w1.acc, a2 = w2.acc;

        int r = t;
        // ---- bulk: fully unrolled 32-row blocks, dual accumulators
        while (seg - r >= 32) {
            const float4* tp = srcq + (size_t)r * NQ;
            float4 m0 = __ldg(&tp[0]);
            float4 m1 = __ldg(&tp[NQ]);
            #pragma unroll
            for (int k = 2; k < 32; k += 2) {
                m0 = f4max(m0, __ldg(&tp[k * NQ]));
                m1 = f4max(m1, __ldg(&tp[(k + 1) * NQ]));
            }
            float4 m = f4max(m0, m1);
            a0 = f4max(a0, m);
            if (in1) a1 = f4max(a1, m);
            if (in2) a2 = f4max(a2, m);
            r += 32;
        }
        // ---- remainder rows
        for (; r < seg; r++) {
            float4 v = __ldg(&srcq[r * NQ]);
            a0 = f4max(a0, v);
            if (in1) a1 = f4max(a1, v);
            if (in2) a2 = f4max(a2, v);
        }
        acc0 = a0; w1.acc = a1; w2.acc = a2;

        t = seg;
        if (t < Tend) {   // transitions at Tend handled by drain
            if (t >= w1.e) win_advance(w1, t, T0, srcq, out_l1, quad);
            if (t >= w2.e) win_advance(w2, t, T0, srcq, out_l2, quad);
        }
    }

    win_drain(w1, T0, Tend, srcq, out_l1, quad);
    win_drain(w2, T0, Tend, srcq, out_l2, quad);

    // Level-0 flush (window 0) — once per chunk.
    float* o0 = out_b + quad * 4;
    atomic_max_f32(o0 + 0, acc0.x);
    atomic_max_f32(o0 + 1, acc0.y);
    atomic_max_f32(o0 + 2, acc0.z);
    atomic_max_f32(o0 + 3, acc0.w);
}

extern "C" void kernel_launch(void* const* d_in, const int* in_sizes, int n_in,
                              void* d_out, int out_size) {
    const float4* seq     = (const float4*)d_in[0];
    const int*    lengths = (const int*)d_in[1];
    float*        out     = (float*)d_out;

    // Initialize output to -inf (harness poisons it to 0xAA before timing).
    spp_init_kernel<<<(out_size + 255) / 256, 256>>>(out, out_size);

    dim3 grid(KT / CHUNK, KB);
    spp_kernel<<<grid, NTHREADS>>>(seq, lengths, out);
}

// round 8
// speedup vs baseline: 1.0509x; 1.0509x over previous
#include <cuda_runtime.h>
#include <math_constants.h>

// Problem constants (fixed shapes from reference)
#define KB 32          // batch
#define KT 8192        // time
#define KC 256         // channels
#define KW 21          // windows: 1 + 4 + 16
#define TILE 32        // rows per CTA
#define NQ  64         // float4 quads per row (KC/4)
#define NTHREADS 64    // 1 thread = 1 quad; every thread sees every row

__device__ __forceinline__ void atomic_max_f32(float* addr, float v) {
    // Order-isomorphic int trick; correct for all non-NaN floats.
    if (v >= 0.0f) {
        atomicMax(reinterpret_cast<int*>(addr), __float_as_int(v));
    } else {
        atomicMin(reinterpret_cast<unsigned int*>(addr), __float_as_uint(v));
    }
}

__global__ void spp_init_kernel(float* __restrict__ out, int n) {
    int i = blockIdx.x * blockDim.x + threadIdx.x;
    if (i < n) out[i] = -CUDART_INF_F;
}

__device__ __forceinline__ float4 f4max(float4 a, float4 b) {
    a.x = fmaxf(a.x, b.x);
    a.y = fmaxf(a.y, b.y);
    a.z = fmaxf(a.z, b.z);
    a.w = fmaxf(a.w, b.w);
    return a;
}

__device__ __forceinline__ void flush4(float* o, float4 a) {
    atomic_max_f32(o + 0, a.x);
    atomic_max_f32(o + 1, a.y);
    atomic_max_f32(o + 2, a.z);
    atomic_max_f32(o + 3, a.w);
}

// For one pyramid level (n windows of length dl, starts rint(stepf*i)):
// flush the max over (window ∩ tile) for every window intersecting [t0,t1).
// Atomics merge partials across CTAs, so no cross-tile state is needed.
// Window-param math is bit-identical to the reference (f32, round-half-even).
__device__ __forceinline__ void process_level(
    int n, int dl, float stepf, int t0, int t1, float4 m,
    const float4* __restrict__ srcq, float* __restrict__ out_lvl, int quad)
{
    // First window index with end > t0 (starts are nondecreasing in i;
    // float estimate + exact monotone fixup).
    int i = 0;
    if (stepf > 0.0f) {
        i = (int)floorf(__fdiv_rn((float)(t0 - dl), stepf));
        i = max(0, min(i, n - 1));
    }
    while (i > 0 && (int)rintf(__fmul_rn(stepf, (float)(i - 1))) + dl > t0) i--;
    while (i < n && (int)rintf(__fmul_rn(stepf, (float)i)) + dl <= t0) i++;

    for (; i < n; i++) {
        const int s = (int)rintf(__fmul_rn(stepf, (float)i));
        if (s >= t1) break;
        const int e  = s + dl;
        const int rb = max(s, t0);
        const int re = min(e, t1);     // re > rb guaranteed (e > t0, dl >= 1)
        float4 a;
        if (rb == t0 && re == t1) {
            a = m;                     // window covers the whole (clipped) tile
        } else {
            a = __ldg(&srcq[rb * NQ]); // boundary window: L1-hot re-reads
            for (int r = rb + 1; r < re; r++)
                a = f4max(a, __ldg(&srcq[r * NQ]));
        }
        flush4(out_lvl + i * KC + quad * 4, a);
    }
}

__global__ __launch_bounds__(NTHREADS, 8) void spp_kernel(
    const float4* __restrict__ seq,     // [B, T, NQ]
    const int* __restrict__ lengths,    // [B]
    float* __restrict__ out)            // [B, W, C]
{
    const int b  = blockIdx.y;
    const int L  = __ldg(&lengths[b]);  // 128-B line, L1-hot after first CTA/SM
    const int t0 = blockIdx.x * TILE;
    if (t0 >= L) return;
    const int t1    = min(t0 + TILE, L);
    const int nrows = t1 - t0;
    const int quad  = threadIdx.x;

    const float4* srcq = seq + (size_t)b * KT * NQ + quad;  // row r -> srcq[r*NQ]
    const float4* tp   = srcq + (size_t)t0 * NQ;
    const float Lf = (float)L;

    // ---- Tile max m over [t0, t1), with window-param math hidden in the
    // load shadow. Full tiles: 16 staged loads -> params -> tree + 16 more.
    float dlf1, step1, dlf2, step2;
    float4 m;
    if (nrows == TILE) {
        float4 v[16];
        #pragma unroll
        for (int k = 0; k < 16; k++) v[k] = __ldg(&tp[k * NQ]);

        // Independent of the loads: executes while they are in flight.
        dlf1  = ceilf(__fmul_rn(Lf, 1.0f / 4.0f)  - 1e-8f);
        step1 = __fdiv_rn(Lf - dlf1, 3.0f);
        dlf2  = ceilf(__fmul_rn(Lf, 1.0f / 16.0f) - 1e-8f);
        step2 = __fdiv_rn(Lf - dlf2, 15.0f);

        float4 a0 = f4max(v[0],  v[1]),  a1 = f4max(v[2],  v[3]);
        float4 a2 = f4max(v[4],  v[5]),  a3 = f4max(v[6],  v[7]);
        a0 = f4max(a0, f4max(v[8],  v[9]));
        a1 = f4max(a1, f4max(v[10], v[11]));
        a2 = f4max(a2, f4max(v[12], v[13]));
        a3 = f4max(a3, f4max(v[14], v[15]));
        #pragma unroll
        for (int k = 16; k < 32; k += 4) {
            a0 = f4max(a0, __ldg(&tp[(k + 0) * NQ]));
            a1 = f4max(a1, __ldg(&tp[(k + 1) * NQ]));
            a2 = f4max(a2, __ldg(&tp[(k + 2) * NQ]));
            a3 = f4max(a3, __ldg(&tp[(k + 3) * NQ]));
        }
        m = f4max(f4max(a0, a1), f4max(a2, a3));
    } else {
        dlf1  = ceilf(__fmul_rn(Lf, 1.0f / 4.0f)  - 1e-8f);
        step1 = __fdiv_rn(Lf - dlf1, 3.0f);
        dlf2  = ceilf(__fmul_rn(Lf, 1.0f / 16.0f) - 1e-8f);
        step2 = __fdiv_rn(Lf - dlf2, 15.0f);
        m = __ldg(&tp[0]);
        for (int r = 1; r < nrows; r++)
            m = f4max(m, __ldg(&tp[r * NQ]));
    }

    float* out_b = out + (size_t)b * KW * KC;

    // Level 0: single window [0, L) always covers the whole tile.
    flush4(out_b + quad * 4, m);

    // Levels 1 and 2.
    process_level(4,  (int)dlf1, step1, t0, t1, m, srcq, out_b + 1 * KC, quad);
    process_level(16, (int)dlf2, step2, t0, t1, m, srcq, out_b + 5 * KC, quad);
}

extern "C" void kernel_launch(void* const* d_in, const int* in_sizes, int n_in,
                              void* d_out, int out_size) {
    const float4* seq     = (const float4*)d_in[0];
    const int*    lengths = (const int*)d_in[1];
    float*        out     = (float*)d_out;

    // Initialize output to -inf (harness poisons it to 0xAA before timing).
    spp_init_kernel<<<(out_size + 255) / 256, 256>>>(out, out_size);

    dim3 grid(KT / TILE, KB);
    spp_kernel<<<grid, NTHREADS>>>(seq, lengths, out);
}